// round 1
// baseline (speedup 1.0000x reference)
#include <cuda_runtime.h>
#include <cuda_bf16.h>
#include <math.h>

// ---------------------------------------------------------------------------
// Problem constants
// ---------------------------------------------------------------------------
#define T_TOKENS 8192   // B*S = 4*2048
#define D_MODEL  1024
#define D_FF     4096
#define N_HEADS  16
#define D_HEAD   64
#define SEQ      2048
#define BATCH    4

// ---------------------------------------------------------------------------
// Scratch (device globals; no allocation allowed)
// ---------------------------------------------------------------------------
__device__ float g_ln  [T_TOKENS * D_MODEL];
__device__ float g_q   [T_TOKENS * D_MODEL];
__device__ float g_k   [T_TOKENS * D_MODEL];
__device__ float g_v   [T_TOKENS * D_MODEL];
__device__ float g_attn[T_TOKENS * D_MODEL];
__device__ float g_x1  [T_TOKENS * D_MODEL];
__device__ float g_h   [T_TOKENS * D_FF];

// ---------------------------------------------------------------------------
// Block reduction helper (256 threads)
// ---------------------------------------------------------------------------
__device__ __forceinline__ float blockReduceSum(float v) {
    __shared__ float sred[32];
    int lane = threadIdx.x & 31;
    int w    = threadIdx.x >> 5;
    #pragma unroll
    for (int o = 16; o > 0; o >>= 1) v += __shfl_xor_sync(0xffffffffu, v, o);
    if (lane == 0) sred[w] = v;
    __syncthreads();
    float r = (threadIdx.x < (blockDim.x >> 5)) ? sred[threadIdx.x] : 0.f;
    if (w == 0) {
        #pragma unroll
        for (int o = 4; o > 0; o >>= 1) r += __shfl_xor_sync(0xffffffffu, r, o);
        if (lane == 0) sred[0] = r;
    }
    __syncthreads();
    float out = sred[0];
    __syncthreads();   // protect sred against the next call's writes
    return out;
}

// ---------------------------------------------------------------------------
// LayerNorm: one block per row (D=1024, 256 threads x float4)
// ---------------------------------------------------------------------------
__global__ __launch_bounds__(256)
void layernorm_kernel(const float* __restrict__ x, const float* __restrict__ g,
                      const float* __restrict__ b, float* __restrict__ out) {
    int row = blockIdx.x;
    int t   = threadIdx.x;
    const float* xr = x + (size_t)row * D_MODEL;
    float4 v = *(const float4*)(xr + t * 4);
    float sum = v.x + v.y + v.z + v.w;
    float mean = blockReduceSum(sum) * (1.f / (float)D_MODEL);
    float dx = v.x - mean, dy = v.y - mean, dz = v.z - mean, dw = v.w - mean;
    float sq = dx * dx + dy * dy + dz * dz + dw * dw;
    float var  = blockReduceSum(sq) * (1.f / (float)D_MODEL);
    float rstd = rsqrtf(var + 1e-6f);
    float4 gv = *(const float4*)(g + t * 4);
    float4 bv = *(const float4*)(b + t * 4);
    float4 o;
    o.x = dx * rstd * gv.x + bv.x;
    o.y = dy * rstd * gv.y + bv.y;
    o.z = dz * rstd * gv.z + bv.z;
    o.w = dw * rstd * gv.w + bv.w;
    *(float4*)(out + (size_t)row * D_MODEL + t * 4) = o;
}

// ---------------------------------------------------------------------------
// SGEMM: C[M,N] = A[M,K] @ W[K,N]  (+bias) (+residual | +gelu)
// 128x128 block tile, BK=16, 256 threads, 8x8 per-thread micro-tile.
// EPI: 0 = bias only, 1 = bias + residual, 2 = bias + gelu(tanh)
// ---------------------------------------------------------------------------
#define BM 128
#define BN 128
#define BK 16
#define TM 8
#define TN 8

__device__ __forceinline__ float gelu_tanh(float x) {
    float x3 = x * x * x;
    return 0.5f * x * (1.f + tanhf(0.7978845608028654f * (x + 0.044715f * x3)));
}

template <int EPI>
__global__ __launch_bounds__(256)
void sgemm_kernel(const float* __restrict__ A, const float* __restrict__ W,
                  const float* __restrict__ bias, const float* __restrict__ res,
                  float* __restrict__ C, int M, int N, int K) {
    __shared__ float As[BK][BM + 4];   // padded: 132 floats = 528 B (16B aligned)
    __shared__ float Bs[BK][BN + 4];

    int tid = threadIdx.x;                 // 0..255
    int bm  = blockIdx.y * BM;
    int bn  = blockIdx.x * BN;
    int tr  = (tid / 16) * TM;             // 0..120
    int tc  = (tid % 16) * TN;             // 0..120

    float acc[TM][TN];
    #pragma unroll
    for (int i = 0; i < TM; i++)
        #pragma unroll
        for (int j = 0; j < TN; j++) acc[i][j] = 0.f;

    for (int k0 = 0; k0 < K; k0 += BK) {
        // Load A tile (BM x BK = 512 float4; 2 per thread), store transposed.
        #pragma unroll
        for (int l = 0; l < 2; l++) {
            int f   = tid + l * 256;
            int row = f >> 2;
            int c4  = f & 3;
            float4 v = *(const float4*)(A + (size_t)(bm + row) * K + k0 + c4 * 4);
            As[c4 * 4 + 0][row] = v.x;
            As[c4 * 4 + 1][row] = v.y;
            As[c4 * 4 + 2][row] = v.z;
            As[c4 * 4 + 3][row] = v.w;
        }
        // Load W tile (BK x BN = 512 float4; 2 per thread).
        #pragma unroll
        for (int l = 0; l < 2; l++) {
            int f  = tid + l * 256;
            int r  = f >> 5;
            int c4 = f & 31;
            float4 v = *(const float4*)(W + (size_t)(k0 + r) * N + bn + c4 * 4);
            *(float4*)(&Bs[r][c4 * 4]) = v;
        }
        __syncthreads();

        #pragma unroll
        for (int kk = 0; kk < BK; kk++) {
            float4 a0 = *(const float4*)(&As[kk][tr]);
            float4 a1 = *(const float4*)(&As[kk][tr + 4]);
            float4 b0 = *(const float4*)(&Bs[kk][tc]);
            float4 b1 = *(const float4*)(&Bs[kk][tc + 4]);
            float a[TM] = {a0.x, a0.y, a0.z, a0.w, a1.x, a1.y, a1.z, a1.w};
            float b[TN] = {b0.x, b0.y, b0.z, b0.w, b1.x, b1.y, b1.z, b1.w};
            #pragma unroll
            for (int i = 0; i < TM; i++)
                #pragma unroll
                for (int j = 0; j < TN; j++)
                    acc[i][j] = fmaf(a[i], b[j], acc[i][j]);
        }
        __syncthreads();
    }

    // Epilogue
    #pragma unroll
    for (int i = 0; i < TM; i++) {
        size_t r = (size_t)(bm + tr + i);
        #pragma unroll
        for (int j = 0; j < TN; j += 4) {
            int c = bn + tc + j;
            float4 o;
            o.x = acc[i][j + 0];
            o.y = acc[i][j + 1];
            o.z = acc[i][j + 2];
            o.w = acc[i][j + 3];
            if (bias) {
                float4 bv = *(const float4*)(bias + c);
                o.x += bv.x; o.y += bv.y; o.z += bv.z; o.w += bv.w;
            }
            if (EPI == 2) {
                o.x = gelu_tanh(o.x); o.y = gelu_tanh(o.y);
                o.z = gelu_tanh(o.z); o.w = gelu_tanh(o.w);
            }
            if (EPI == 1) {
                float4 rv = *(const float4*)(res + r * N + c);
                o.x += rv.x; o.y += rv.y; o.z += rv.z; o.w += rv.w;
            }
            *(float4*)(C + r * N + c) = o;
        }
    }
}

// ---------------------------------------------------------------------------
// Flash attention (causal). One thread per query row; Q,O in registers;
// K/V tiles (32x64) staged in smem, broadcast-read via LDS.128.
// Grid: (SEQ/64, B*H); block: 64 threads.
// ---------------------------------------------------------------------------
#define FA_BQ 64
#define FA_BK 32

__global__ __launch_bounds__(64)
void flash_kernel(const float* __restrict__ Q, const float* __restrict__ K,
                  const float* __restrict__ V, float* __restrict__ O) {
    __shared__ float Ks[FA_BK][D_HEAD];
    __shared__ float Vs[FA_BK][D_HEAD];

    int qt  = blockIdx.x;
    int bh  = blockIdx.y;
    int b   = bh >> 4;
    int h   = bh & 15;
    int tid = threadIdx.x;
    int qrow = qt * FA_BQ + tid;   // sequence position of this thread's query

    size_t qbase = ((size_t)(b * SEQ + qrow)) * D_MODEL + h * D_HEAD;

    float q[D_HEAD], o[D_HEAD];
    #pragma unroll
    for (int d = 0; d < D_HEAD; d += 4) {
        float4 v = *(const float4*)(Q + qbase + d);
        q[d] = v.x; q[d + 1] = v.y; q[d + 2] = v.z; q[d + 3] = v.w;
        o[d] = 0.f; o[d + 1] = 0.f; o[d + 2] = 0.f; o[d + 3] = 0.f;
    }

    float m = -1e30f, l = 0.f;
    int ktiles = qt * 2 + 2;   // cover rows [0, qt*64+64) with 32-row tiles

    for (int kt = 0; kt < ktiles; kt++) {
        // Load K,V tile: 32 rows x 64 cols = 512 float4 each; 8 per thread.
        #pragma unroll
        for (int l2 = 0; l2 < 8; l2++) {
            int f  = tid + l2 * 64;
            int r  = f >> 4;
            int c4 = f & 15;
            size_t gb = ((size_t)(b * SEQ + kt * FA_BK + r)) * D_MODEL + h * D_HEAD + c4 * 4;
            *(float4*)(&Ks[r][c4 * 4]) = *(const float4*)(K + gb);
            *(float4*)(&Vs[r][c4 * 4]) = *(const float4*)(V + gb);
        }
        __syncthreads();

        float s[FA_BK];
        #pragma unroll
        for (int j = 0; j < FA_BK; j++) {
            float acc = 0.f;
            #pragma unroll
            for (int d = 0; d < D_HEAD; d += 4) {
                float4 kv = *(const float4*)(&Ks[j][d]);
                acc = fmaf(q[d],     kv.x, acc);
                acc = fmaf(q[d + 1], kv.y, acc);
                acc = fmaf(q[d + 2], kv.z, acc);
                acc = fmaf(q[d + 3], kv.w, acc);
            }
            int kj = kt * FA_BK + j;
            s[j] = (kj <= qrow) ? acc * 0.125f : -1e30f;   // 1/sqrt(64)
        }

        float mt = m;
        #pragma unroll
        for (int j = 0; j < FA_BK; j++) mt = fmaxf(mt, s[j]);
        float scale = __expf(m - mt);
        l *= scale;
        #pragma unroll
        for (int d = 0; d < D_HEAD; d++) o[d] *= scale;

        #pragma unroll
        for (int j = 0; j < FA_BK; j++) {
            float p = __expf(s[j] - mt);
            l += p;
            #pragma unroll
            for (int d = 0; d < D_HEAD; d += 4) {
                float4 vv = *(const float4*)(&Vs[j][d]);
                o[d]     = fmaf(p, vv.x, o[d]);
                o[d + 1] = fmaf(p, vv.y, o[d + 1]);
                o[d + 2] = fmaf(p, vv.z, o[d + 2]);
                o[d + 3] = fmaf(p, vv.w, o[d + 3]);
            }
        }
        m = mt;
        __syncthreads();
    }

    float inv = 1.f / l;
    #pragma unroll
    for (int d = 0; d < D_HEAD; d += 4) {
        float4 v;
        v.x = o[d] * inv; v.y = o[d + 1] * inv;
        v.z = o[d + 2] * inv; v.w = o[d + 3] * inv;
        *(float4*)(O + qbase + d) = v;
    }
}

// ---------------------------------------------------------------------------
// Launch
// ---------------------------------------------------------------------------
extern "C" void kernel_launch(void* const* d_in, const int* in_sizes, int n_in,
                              void* d_out, int out_size) {
    const float* x   = (const float*)d_in[0];
    const float* Wq  = (const float*)d_in[1];
    const float* bq  = (const float*)d_in[2];
    const float* Wk  = (const float*)d_in[3];
    const float* bk  = (const float*)d_in[4];
    const float* Wv  = (const float*)d_in[5];
    const float* bv  = (const float*)d_in[6];
    const float* Wo  = (const float*)d_in[7];
    const float* W1  = (const float*)d_in[8];
    const float* b1  = (const float*)d_in[9];
    const float* W2  = (const float*)d_in[10];
    const float* b2  = (const float*)d_in[11];
    const float* g1  = (const float*)d_in[12];
    const float* be1 = (const float*)d_in[13];
    const float* g2  = (const float*)d_in[14];
    const float* be2 = (const float*)d_in[15];
    float* out = (float*)d_out;

    float *ln, *q, *k, *v, *attn, *x1, *h;
    cudaGetSymbolAddress((void**)&ln,   g_ln);
    cudaGetSymbolAddress((void**)&q,    g_q);
    cudaGetSymbolAddress((void**)&k,    g_k);
    cudaGetSymbolAddress((void**)&v,    g_v);
    cudaGetSymbolAddress((void**)&attn, g_attn);
    cudaGetSymbolAddress((void**)&x1,   g_x1);
    cudaGetSymbolAddress((void**)&h,    g_h);

    dim3 gemm_d(D_MODEL / BN, T_TOKENS / BM);   // (8, 64)
    dim3 gemm_ff1(D_FF / BN, T_TOKENS / BM);    // (32, 64)

    // 1) ln1 = LN(x; g1, beta1)
    layernorm_kernel<<<T_TOKENS, 256>>>(x, g1, be1, ln);
    // 2) Q,K,V = ln1 @ W* + b*
    sgemm_kernel<0><<<gemm_d, 256>>>(ln, Wq, bq, nullptr, q, T_TOKENS, D_MODEL, D_MODEL);
    sgemm_kernel<0><<<gemm_d, 256>>>(ln, Wk, bk, nullptr, k, T_TOKENS, D_MODEL, D_MODEL);
    sgemm_kernel<0><<<gemm_d, 256>>>(ln, Wv, bv, nullptr, v, T_TOKENS, D_MODEL, D_MODEL);
    // 3) causal flash attention
    flash_kernel<<<dim3(SEQ / FA_BQ, BATCH * N_HEADS), 64>>>(q, k, v, attn);
    // 4) x1 = x + attn @ Wo      (no bias on o-proj)
    sgemm_kernel<1><<<gemm_d, 256>>>(attn, Wo, nullptr, x, x1, T_TOKENS, D_MODEL, D_MODEL);
    // 5) ln2 = LN(x1; g2, beta2)
    layernorm_kernel<<<T_TOKENS, 256>>>(x1, g2, be2, ln);
    // 6) h = gelu(ln2 @ W1 + b1)
    sgemm_kernel<2><<<gemm_ff1, 256>>>(ln, W1, b1, nullptr, h, T_TOKENS, D_FF, D_MODEL);
    // 7) out = x1 + h @ W2 + b2
    sgemm_kernel<1><<<gemm_d, 256>>>(h, W2, b2, x1, out, T_TOKENS, D_MODEL, D_FF);
}

// round 2
// speedup vs baseline: 1.6606x; 1.6606x over previous
#include <cuda_runtime.h>
#include <cuda_bf16.h>
#include <math.h>

// ---------------------------------------------------------------------------
// Problem constants
// ---------------------------------------------------------------------------
#define T_TOKENS 8192   // B*S = 4*2048
#define D_MODEL  1024
#define D_FF     4096
#define N_HEADS  16
#define D_HEAD   64
#define SEQ      2048
#define BATCH    4

// ---------------------------------------------------------------------------
// Scratch (device globals; no allocation allowed)
// ---------------------------------------------------------------------------
__device__ float g_ln  [T_TOKENS * D_MODEL];
__device__ float g_q   [T_TOKENS * D_MODEL];
__device__ float g_k   [T_TOKENS * D_MODEL];
__device__ float g_v   [T_TOKENS * D_MODEL];
__device__ float g_attn[T_TOKENS * D_MODEL];
__device__ float g_x1  [T_TOKENS * D_MODEL];
__device__ float g_h   [T_TOKENS * D_FF];

// ---------------------------------------------------------------------------
// Block reduction helper (256 threads)
// ---------------------------------------------------------------------------
__device__ __forceinline__ float blockReduceSum(float v) {
    __shared__ float sred[32];
    int lane = threadIdx.x & 31;
    int w    = threadIdx.x >> 5;
    #pragma unroll
    for (int o = 16; o > 0; o >>= 1) v += __shfl_xor_sync(0xffffffffu, v, o);
    if (lane == 0) sred[w] = v;
    __syncthreads();
    float r = (threadIdx.x < (blockDim.x >> 5)) ? sred[threadIdx.x] : 0.f;
    if (w == 0) {
        #pragma unroll
        for (int o = 4; o > 0; o >>= 1) r += __shfl_xor_sync(0xffffffffu, r, o);
        if (lane == 0) sred[0] = r;
    }
    __syncthreads();
    float out = sred[0];
    __syncthreads();
    return out;
}

// ---------------------------------------------------------------------------
// LayerNorm: one block per row (D=1024, 256 threads x float4)
// ---------------------------------------------------------------------------
__global__ __launch_bounds__(256)
void layernorm_kernel(const float* __restrict__ x, const float* __restrict__ g,
                      const float* __restrict__ b, float* __restrict__ out) {
    int row = blockIdx.x;
    int t   = threadIdx.x;
    const float* xr = x + (size_t)row * D_MODEL;
    float4 v = *(const float4*)(xr + t * 4);
    float sum = v.x + v.y + v.z + v.w;
    float mean = blockReduceSum(sum) * (1.f / (float)D_MODEL);
    float dx = v.x - mean, dy = v.y - mean, dz = v.z - mean, dw = v.w - mean;
    float sq = dx * dx + dy * dy + dz * dz + dw * dw;
    float var  = blockReduceSum(sq) * (1.f / (float)D_MODEL);
    float rstd = rsqrtf(var + 1e-6f);
    float4 gv = *(const float4*)(g + t * 4);
    float4 bv = *(const float4*)(b + t * 4);
    float4 o;
    o.x = dx * rstd * gv.x + bv.x;
    o.y = dy * rstd * gv.y + bv.y;
    o.z = dz * rstd * gv.z + bv.z;
    o.w = dw * rstd * gv.w + bv.w;
    *(float4*)(out + (size_t)row * D_MODEL + t * 4) = o;
}

// ---------------------------------------------------------------------------
// TF32 tensor-core GEMM: C[M,N] = A[M,K] @ W[K,N]  (+bias) (+residual | +gelu)
// 128x128 block tile, BK=32, 256 threads = 8 warps (4x2), warp tile 32x64.
// mma.sync.aligned.m16n8k8.row.col.f32.tf32.tf32.f32
// EPI: 0 = bias only, 1 = bias + residual, 2 = bias + gelu(tanh)
// ---------------------------------------------------------------------------
#define BM 128
#define BN 128
#define BK 32
#define SMPAD 4   // stride 132 floats: LDS bank conflict degree <= 2

__device__ __forceinline__ float gelu_tanh(float x) {
    float x3 = x * x * x;
    return 0.5f * x * (1.f + tanhf(0.7978845608028654f * (x + 0.044715f * x3)));
}

__device__ __forceinline__ unsigned f2tf32(float x) {
    unsigned r;
    asm("cvt.rna.tf32.f32 %0, %1;" : "=r"(r) : "f"(x));
    return r;
}

__device__ __forceinline__ void mma_tf32(float& c0, float& c1, float& c2, float& c3,
                                         unsigned a0, unsigned a1, unsigned a2, unsigned a3,
                                         unsigned b0, unsigned b1) {
    asm volatile(
        "mma.sync.aligned.m16n8k8.row.col.f32.tf32.tf32.f32 "
        "{%0,%1,%2,%3}, {%4,%5,%6,%7}, {%8,%9}, {%0,%1,%2,%3};"
        : "+f"(c0), "+f"(c1), "+f"(c2), "+f"(c3)
        : "r"(a0), "r"(a1), "r"(a2), "r"(a3), "r"(b0), "r"(b1));
}

template <int EPI>
__global__ __launch_bounds__(256)
void gemm_tf32_kernel(const float* __restrict__ A, const float* __restrict__ W,
                      const float* __restrict__ bias, const float* __restrict__ res,
                      float* __restrict__ C, int M, int N, int K) {
    __shared__ unsigned As[BK][BM + SMPAD];   // tf32 bits, [k][m]
    __shared__ unsigned Bs[BK][BN + SMPAD];   // tf32 bits, [k][n]

    int tid  = threadIdx.x;
    int lane = tid & 31;
    int wid  = tid >> 5;            // 0..7
    int g    = lane >> 2;           // groupID 0..7
    int tig  = lane & 3;            // threadID in group 0..3

    int bm = blockIdx.y * BM;
    int bn = blockIdx.x * BN;
    int rowBase = (wid >> 1) * 32;  // warp M offset within block
    int colBase = (wid & 1) * 64;   // warp N offset within block

    // accumulators: 2 m-tiles x 8 n-tiles x 4 regs
    float c[2][8][4];
    #pragma unroll
    for (int mt = 0; mt < 2; mt++)
        #pragma unroll
        for (int nt = 0; nt < 8; nt++)
            #pragma unroll
            for (int r = 0; r < 4; r++) c[mt][nt][r] = 0.f;

    for (int k0 = 0; k0 < K; k0 += BK) {
        // Load A tile 128x32 (1024 float4; 4 per thread), store transposed [k][m]
        #pragma unroll
        for (int l = 0; l < 4; l++) {
            int f   = tid + l * 256;
            int row = f >> 3;
            int c4  = (f & 7) * 4;
            float4 v = *(const float4*)(A + (size_t)(bm + row) * K + k0 + c4);
            As[c4 + 0][row] = f2tf32(v.x);
            As[c4 + 1][row] = f2tf32(v.y);
            As[c4 + 2][row] = f2tf32(v.z);
            As[c4 + 3][row] = f2tf32(v.w);
        }
        // Load B tile 32x128 (1024 float4; 4 per thread), [k][n]
        #pragma unroll
        for (int l = 0; l < 4; l++) {
            int f  = tid + l * 256;
            int r  = f >> 5;
            int c4 = (f & 31) * 4;
            float4 v = *(const float4*)(W + (size_t)(k0 + r) * N + bn + c4);
            Bs[r][c4 + 0] = f2tf32(v.x);
            Bs[r][c4 + 1] = f2tf32(v.y);
            Bs[r][c4 + 2] = f2tf32(v.z);
            Bs[r][c4 + 3] = f2tf32(v.w);
        }
        __syncthreads();

        #pragma unroll
        for (int ks = 0; ks < BK / 8; ks++) {
            int kb = ks * 8;
            // A fragments for 2 m-tiles
            unsigned a[2][4];
            #pragma unroll
            for (int mt = 0; mt < 2; mt++) {
                int m0 = rowBase + mt * 16 + g;
                a[mt][0] = As[kb + tig][m0];
                a[mt][1] = As[kb + tig][m0 + 8];
                a[mt][2] = As[kb + tig + 4][m0];
                a[mt][3] = As[kb + tig + 4][m0 + 8];
            }
            // B fragments for 8 n-tiles
            unsigned b[8][2];
            #pragma unroll
            for (int nt = 0; nt < 8; nt++) {
                int n0 = colBase + nt * 8 + g;
                b[nt][0] = Bs[kb + tig][n0];
                b[nt][1] = Bs[kb + tig + 4][n0];
            }
            #pragma unroll
            for (int mt = 0; mt < 2; mt++)
                #pragma unroll
                for (int nt = 0; nt < 8; nt++)
                    mma_tf32(c[mt][nt][0], c[mt][nt][1], c[mt][nt][2], c[mt][nt][3],
                             a[mt][0], a[mt][1], a[mt][2], a[mt][3],
                             b[nt][0], b[nt][1]);
        }
        __syncthreads();
    }

    // Epilogue: thread owns rows {g, g+8} per m-tile, cols {2*tig, 2*tig+1} per n-tile
    #pragma unroll
    for (int mt = 0; mt < 2; mt++) {
        #pragma unroll
        for (int half = 0; half < 2; half++) {
            size_t row = (size_t)(bm + rowBase + mt * 16 + g + half * 8);
            #pragma unroll
            for (int nt = 0; nt < 8; nt++) {
                int col = bn + colBase + nt * 8 + tig * 2;
                float v0 = c[mt][nt][half * 2 + 0];
                float v1 = c[mt][nt][half * 2 + 1];
                if (bias) {
                    v0 += bias[col];
                    v1 += bias[col + 1];
                }
                if (EPI == 2) { v0 = gelu_tanh(v0); v1 = gelu_tanh(v1); }
                if (EPI == 1) {
                    const float2 rv = *(const float2*)(res + row * N + col);
                    v0 += rv.x; v1 += rv.y;
                }
                float2 o; o.x = v0; o.y = v1;
                *(float2*)(C + row * N + col) = o;
            }
        }
    }
}

// ---------------------------------------------------------------------------
// Flash attention (causal). One thread per query row; Q,O in registers;
// K/V tiles (32x64) staged in smem, broadcast-read via LDS.128.
// Grid: (SEQ/128, B*H); block: 128 threads.
// ---------------------------------------------------------------------------
#define FA_BQ 128
#define FA_BK 32

__global__ __launch_bounds__(128)
void flash_kernel(const float* __restrict__ Q, const float* __restrict__ K,
                  const float* __restrict__ V, float* __restrict__ O) {
    __shared__ float Ks[FA_BK][D_HEAD];
    __shared__ float Vs[FA_BK][D_HEAD];

    int qt  = blockIdx.x;
    int bh  = blockIdx.y;
    int b   = bh >> 4;
    int h   = bh & 15;
    int tid = threadIdx.x;
    int qrow = qt * FA_BQ + tid;

    size_t qbase = ((size_t)(b * SEQ + qrow)) * D_MODEL + h * D_HEAD;

    float q[D_HEAD], o[D_HEAD];
    #pragma unroll
    for (int d = 0; d < D_HEAD; d += 4) {
        float4 v = *(const float4*)(Q + qbase + d);
        q[d] = v.x; q[d + 1] = v.y; q[d + 2] = v.z; q[d + 3] = v.w;
        o[d] = 0.f; o[d + 1] = 0.f; o[d + 2] = 0.f; o[d + 3] = 0.f;
    }

    float m = -1e30f, l = 0.f;
    int ktiles = (qt + 1) * (FA_BQ / FA_BK);

    for (int kt = 0; kt < ktiles; kt++) {
        // Load K,V tile: 32 rows x 64 cols = 512 float4 each; 4 per thread.
        #pragma unroll
        for (int l2 = 0; l2 < 4; l2++) {
            int f  = tid + l2 * 128;
            int r  = f >> 4;
            int c4 = (f & 15) * 4;
            size_t gb = ((size_t)(b * SEQ + kt * FA_BK + r)) * D_MODEL + h * D_HEAD + c4;
            *(float4*)(&Ks[r][c4]) = *(const float4*)(K + gb);
            *(float4*)(&Vs[r][c4]) = *(const float4*)(V + gb);
        }
        __syncthreads();

        float s[FA_BK];
        #pragma unroll
        for (int j = 0; j < FA_BK; j++) {
            float acc = 0.f;
            #pragma unroll
            for (int d = 0; d < D_HEAD; d += 4) {
                float4 kv = *(const float4*)(&Ks[j][d]);
                acc = fmaf(q[d],     kv.x, acc);
                acc = fmaf(q[d + 1], kv.y, acc);
                acc = fmaf(q[d + 2], kv.z, acc);
                acc = fmaf(q[d + 3], kv.w, acc);
            }
            int kj = kt * FA_BK + j;
            s[j] = (kj <= qrow) ? acc * 0.125f : -1e30f;
        }

        float mt = m;
        #pragma unroll
        for (int j = 0; j < FA_BK; j++) mt = fmaxf(mt, s[j]);
        float scale = __expf(m - mt);
        l *= scale;
        #pragma unroll
        for (int d = 0; d < D_HEAD; d++) o[d] *= scale;

        #pragma unroll
        for (int j = 0; j < FA_BK; j++) {
            float p = __expf(s[j] - mt);
            l += p;
            #pragma unroll
            for (int d = 0; d < D_HEAD; d += 4) {
                float4 vv = *(const float4*)(&Vs[j][d]);
                o[d]     = fmaf(p, vv.x, o[d]);
                o[d + 1] = fmaf(p, vv.y, o[d + 1]);
                o[d + 2] = fmaf(p, vv.z, o[d + 2]);
                o[d + 3] = fmaf(p, vv.w, o[d + 3]);
            }
        }
        m = mt;
        __syncthreads();
    }

    float inv = 1.f / l;
    #pragma unroll
    for (int d = 0; d < D_HEAD; d += 4) {
        float4 v;
        v.x = o[d] * inv; v.y = o[d + 1] * inv;
        v.z = o[d + 2] * inv; v.w = o[d + 3] * inv;
        *(float4*)(O + qbase + d) = v;
    }
}

// ---------------------------------------------------------------------------
// Launch
// ---------------------------------------------------------------------------
extern "C" void kernel_launch(void* const* d_in, const int* in_sizes, int n_in,
                              void* d_out, int out_size) {
    const float* x   = (const float*)d_in[0];
    const float* Wq  = (const float*)d_in[1];
    const float* bq  = (const float*)d_in[2];
    const float* Wk  = (const float*)d_in[3];
    const float* bk  = (const float*)d_in[4];
    const float* Wv  = (const float*)d_in[5];
    const float* bv  = (const float*)d_in[6];
    const float* Wo  = (const float*)d_in[7];
    const float* W1  = (const float*)d_in[8];
    const float* b1  = (const float*)d_in[9];
    const float* W2  = (const float*)d_in[10];
    const float* b2  = (const float*)d_in[11];
    const float* g1  = (const float*)d_in[12];
    const float* be1 = (const float*)d_in[13];
    const float* g2  = (const float*)d_in[14];
    const float* be2 = (const float*)d_in[15];
    float* out = (float*)d_out;

    float *ln, *q, *k, *v, *attn, *x1, *h;
    cudaGetSymbolAddress((void**)&ln,   g_ln);
    cudaGetSymbolAddress((void**)&q,    g_q);
    cudaGetSymbolAddress((void**)&k,    g_k);
    cudaGetSymbolAddress((void**)&v,    g_v);
    cudaGetSymbolAddress((void**)&attn, g_attn);
    cudaGetSymbolAddress((void**)&x1,   g_x1);
    cudaGetSymbolAddress((void**)&h,    g_h);

    dim3 gemm_d(D_MODEL / BN, T_TOKENS / BM);   // (8, 64)
    dim3 gemm_ff1(D_FF / BN, T_TOKENS / BM);    // (32, 64)

    // 1) ln1 = LN(x; g1, beta1)
    layernorm_kernel<<<T_TOKENS, 256>>>(x, g1, be1, ln);
    // 2) Q,K,V = ln1 @ W* + b*
    gemm_tf32_kernel<0><<<gemm_d, 256>>>(ln, Wq, bq, nullptr, q, T_TOKENS, D_MODEL, D_MODEL);
    gemm_tf32_kernel<0><<<gemm_d, 256>>>(ln, Wk, bk, nullptr, k, T_TOKENS, D_MODEL, D_MODEL);
    gemm_tf32_kernel<0><<<gemm_d, 256>>>(ln, Wv, bv, nullptr, v, T_TOKENS, D_MODEL, D_MODEL);
    // 3) causal flash attention
    flash_kernel<<<dim3(SEQ / FA_BQ, BATCH * N_HEADS), FA_BQ>>>(q, k, v, attn);
    // 4) x1 = x + attn @ Wo      (no bias on o-proj)
    gemm_tf32_kernel<1><<<gemm_d, 256>>>(attn, Wo, nullptr, x, x1, T_TOKENS, D_MODEL, D_MODEL);
    // 5) ln2 = LN(x1; g2, beta2)
    layernorm_kernel<<<T_TOKENS, 256>>>(x1, g2, be2, ln);
    // 6) h = gelu(ln2 @ W1 + b1)
    gemm_tf32_kernel<2><<<gemm_ff1, 256>>>(ln, W1, b1, nullptr, h, T_TOKENS, D_FF, D_MODEL);
    // 7) out = x1 + h @ W2 + b2
    gemm_tf32_kernel<1><<<gemm_d, 256>>>(h, W2, b2, x1, out, T_TOKENS, D_MODEL, D_FF);
}

// round 3
// speedup vs baseline: 2.9200x; 1.7584x over previous
#include <cuda_runtime.h>
#include <cuda_bf16.h>
#include <math.h>

// ---------------------------------------------------------------------------
// Problem constants
// ---------------------------------------------------------------------------
#define T_TOKENS 8192   // B*S = 4*2048
#define D_MODEL  1024
#define D_FF     4096
#define N_HEADS  16
#define D_HEAD   64
#define SEQ      2048
#define BATCH    4

// ---------------------------------------------------------------------------
// Scratch (device globals; no allocation allowed)
// ---------------------------------------------------------------------------
__device__ float g_ln  [T_TOKENS * D_MODEL];
__device__ float g_q   [T_TOKENS * D_MODEL];
__device__ float g_k   [T_TOKENS * D_MODEL];
__device__ float g_v   [T_TOKENS * D_MODEL];
__device__ float g_attn[T_TOKENS * D_MODEL];
__device__ float g_x1  [T_TOKENS * D_MODEL];
__device__ float g_h   [T_TOKENS * D_FF];

// ---------------------------------------------------------------------------
// Common helpers
// ---------------------------------------------------------------------------
__device__ __forceinline__ unsigned f2tf32(float x) {
    unsigned r;
    asm("cvt.rna.tf32.f32 %0, %1;" : "=r"(r) : "f"(x));
    return r;
}

__device__ __forceinline__ void mma_tf32(float& c0, float& c1, float& c2, float& c3,
                                         unsigned a0, unsigned a1, unsigned a2, unsigned a3,
                                         unsigned b0, unsigned b1) {
    asm volatile(
        "mma.sync.aligned.m16n8k8.row.col.f32.tf32.tf32.f32 "
        "{%0,%1,%2,%3}, {%4,%5,%6,%7}, {%8,%9}, {%0,%1,%2,%3};"
        : "+f"(c0), "+f"(c1), "+f"(c2), "+f"(c3)
        : "r"(a0), "r"(a1), "r"(a2), "r"(a3), "r"(b0), "r"(b1));
}

__device__ __forceinline__ float gelu_tanh(float x) {
    float x3 = x * x * x;
    return 0.5f * x * (1.f + tanhf(0.7978845608028654f * (x + 0.044715f * x3)));
}

// ---------------------------------------------------------------------------
// Block reduction helper (256 threads)
// ---------------------------------------------------------------------------
__device__ __forceinline__ float blockReduceSum(float v) {
    __shared__ float sred[32];
    int lane = threadIdx.x & 31;
    int w    = threadIdx.x >> 5;
    #pragma unroll
    for (int o = 16; o > 0; o >>= 1) v += __shfl_xor_sync(0xffffffffu, v, o);
    if (lane == 0) sred[w] = v;
    __syncthreads();
    float r = (threadIdx.x < (blockDim.x >> 5)) ? sred[threadIdx.x] : 0.f;
    if (w == 0) {
        #pragma unroll
        for (int o = 4; o > 0; o >>= 1) r += __shfl_xor_sync(0xffffffffu, r, o);
        if (lane == 0) sred[0] = r;
    }
    __syncthreads();
    float out = sred[0];
    __syncthreads();
    return out;
}

// ---------------------------------------------------------------------------
// LayerNorm: one block per row (D=1024, 256 threads x float4)
// ---------------------------------------------------------------------------
__global__ __launch_bounds__(256)
void layernorm_kernel(const float* __restrict__ x, const float* __restrict__ g,
                      const float* __restrict__ b, float* __restrict__ out) {
    int row = blockIdx.x;
    int t   = threadIdx.x;
    const float* xr = x + (size_t)row * D_MODEL;
    float4 v = *(const float4*)(xr + t * 4);
    float sum = v.x + v.y + v.z + v.w;
    float mean = blockReduceSum(sum) * (1.f / (float)D_MODEL);
    float dx = v.x - mean, dy = v.y - mean, dz = v.z - mean, dw = v.w - mean;
    float sq = dx * dx + dy * dy + dz * dz + dw * dw;
    float var  = blockReduceSum(sq) * (1.f / (float)D_MODEL);
    float rstd = rsqrtf(var + 1e-6f);
    float4 gv = *(const float4*)(g + t * 4);
    float4 bv = *(const float4*)(b + t * 4);
    float4 o;
    o.x = dx * rstd * gv.x + bv.x;
    o.y = dy * rstd * gv.y + bv.y;
    o.z = dz * rstd * gv.z + bv.z;
    o.w = dw * rstd * gv.w + bv.w;
    *(float4*)(out + (size_t)row * D_MODEL + t * 4) = o;
}

// ---------------------------------------------------------------------------
// TF32 tensor-core GEMM with 2-stage smem double buffering.
// C[M,N] = A[M,K] @ W[K,N]  (+bias) (+residual | +gelu)
// 128x128 block tile, BK=16 per stage, 256 threads = 8 warps, warp 32x64.
// EPI: 0 = bias only, 1 = bias + residual, 2 = bias + gelu(tanh)
// ---------------------------------------------------------------------------
#define BM 128
#define BN 128
#define GBK 16
#define SMPAD 4

template <int EPI>
__global__ __launch_bounds__(256)
void gemm_tf32_kernel(const float* __restrict__ A, const float* __restrict__ W,
                      const float* __restrict__ bias, const float* __restrict__ res,
                      float* __restrict__ C, int M, int N, int K) {
    __shared__ unsigned As[2][GBK][BM + SMPAD];
    __shared__ unsigned Bs[2][GBK][BN + SMPAD];

    int tid  = threadIdx.x;
    int lane = tid & 31;
    int wid  = tid >> 5;
    int g    = lane >> 2;
    int tig  = lane & 3;

    int bm = blockIdx.y * BM;
    int bn = blockIdx.x * BN;
    int rowBase = (wid >> 1) * 32;
    int colBase = (wid & 1) * 64;

    float c[2][8][4];
    #pragma unroll
    for (int mt = 0; mt < 2; mt++)
        #pragma unroll
        for (int nt = 0; nt < 8; nt++)
            #pragma unroll
            for (int r = 0; r < 4; r++) c[mt][nt][r] = 0.f;

    // loader indexing
    int arow = tid >> 2;                 // A: rows tid/4, tid/4 (+64 via l)
    int ac4  = (tid & 3) * 4;
    int brow = tid >> 5;                 // B: rows 0..7 (+8 via l)
    int bc4  = (tid & 31) * 4;

    float4 av[2], bv[2];
    // prologue: LDG tile 0
    #pragma unroll
    for (int l = 0; l < 2; l++) {
        av[l] = *(const float4*)(A + (size_t)(bm + arow + l * 64) * K + ac4);
        bv[l] = *(const float4*)(W + (size_t)(brow + l * 8) * N + bn + bc4);
    }
    // STS stage 0
    #pragma unroll
    for (int l = 0; l < 2; l++) {
        int r = arow + l * 64;
        As[0][ac4 + 0][r] = f2tf32(av[l].x);
        As[0][ac4 + 1][r] = f2tf32(av[l].y);
        As[0][ac4 + 2][r] = f2tf32(av[l].z);
        As[0][ac4 + 3][r] = f2tf32(av[l].w);
        int rb = brow + l * 8;
        Bs[0][rb][bc4 + 0] = f2tf32(bv[l].x);
        Bs[0][rb][bc4 + 1] = f2tf32(bv[l].y);
        Bs[0][rb][bc4 + 2] = f2tf32(bv[l].z);
        Bs[0][rb][bc4 + 3] = f2tf32(bv[l].w);
    }
    __syncthreads();

    int nIter = K / GBK;
    for (int it = 0; it < nIter; it++) {
        int cur = it & 1;
        bool hasNext = (it + 1 < nIter);
        if (hasNext) {
            int k0 = (it + 1) * GBK;
            #pragma unroll
            for (int l = 0; l < 2; l++) {
                av[l] = *(const float4*)(A + (size_t)(bm + arow + l * 64) * K + k0 + ac4);
                bv[l] = *(const float4*)(W + (size_t)(k0 + brow + l * 8) * N + bn + bc4);
            }
        }

        #pragma unroll
        for (int ks = 0; ks < GBK / 8; ks++) {
            int kb = ks * 8;
            unsigned a[2][4];
            #pragma unroll
            for (int mt = 0; mt < 2; mt++) {
                int m0 = rowBase + mt * 16 + g;
                a[mt][0] = As[cur][kb + tig][m0];
                a[mt][1] = As[cur][kb + tig][m0 + 8];
                a[mt][2] = As[cur][kb + tig + 4][m0];
                a[mt][3] = As[cur][kb + tig + 4][m0 + 8];
            }
            unsigned b[8][2];
            #pragma unroll
            for (int nt = 0; nt < 8; nt++) {
                int n0 = colBase + nt * 8 + g;
                b[nt][0] = Bs[cur][kb + tig][n0];
                b[nt][1] = Bs[cur][kb + tig + 4][n0];
            }
            #pragma unroll
            for (int mt = 0; mt < 2; mt++)
                #pragma unroll
                for (int nt = 0; nt < 8; nt++)
                    mma_tf32(c[mt][nt][0], c[mt][nt][1], c[mt][nt][2], c[mt][nt][3],
                             a[mt][0], a[mt][1], a[mt][2], a[mt][3],
                             b[nt][0], b[nt][1]);
        }

        if (hasNext) {
            int nxt = 1 - cur;
            #pragma unroll
            for (int l = 0; l < 2; l++) {
                int r = arow + l * 64;
                As[nxt][ac4 + 0][r] = f2tf32(av[l].x);
                As[nxt][ac4 + 1][r] = f2tf32(av[l].y);
                As[nxt][ac4 + 2][r] = f2tf32(av[l].z);
                As[nxt][ac4 + 3][r] = f2tf32(av[l].w);
                int rb = brow + l * 8;
                Bs[nxt][rb][bc4 + 0] = f2tf32(bv[l].x);
                Bs[nxt][rb][bc4 + 1] = f2tf32(bv[l].y);
                Bs[nxt][rb][bc4 + 2] = f2tf32(bv[l].z);
                Bs[nxt][rb][bc4 + 3] = f2tf32(bv[l].w);
            }
        }
        __syncthreads();
    }

    // Epilogue
    #pragma unroll
    for (int mt = 0; mt < 2; mt++) {
        #pragma unroll
        for (int half = 0; half < 2; half++) {
            size_t row = (size_t)(bm + rowBase + mt * 16 + g + half * 8);
            #pragma unroll
            for (int nt = 0; nt < 8; nt++) {
                int col = bn + colBase + nt * 8 + tig * 2;
                float v0 = c[mt][nt][half * 2 + 0];
                float v1 = c[mt][nt][half * 2 + 1];
                if (bias) {
                    v0 += bias[col];
                    v1 += bias[col + 1];
                }
                if (EPI == 2) { v0 = gelu_tanh(v0); v1 = gelu_tanh(v1); }
                if (EPI == 1) {
                    const float2 rv = *(const float2*)(res + row * N + col);
                    v0 += rv.x; v1 += rv.y;
                }
                float2 o; o.x = v0; o.y = v1;
                *(float2*)(C + row * N + col) = o;
            }
        }
    }
}

// ---------------------------------------------------------------------------
// Flash attention v2 (causal), tf32 tensor cores.
// Block = 128 threads (4 warps). BQ=64 (warp owns 16 rows), BK=64 keys/tile.
// Q fragments resident in registers; K,V tiles in smem (tf32).
// P goes through a warp-private smem region (aliased onto Ks, which is dead
// after the S-mma) to convert C-fragment layout -> A-fragment layout.
// Softmax in log2 domain (exp2f).
// ---------------------------------------------------------------------------
#define FB_Q 64
#define FB_K 64
#define KS_ST 68   // 4g+tig banks: conflict-free fragment reads
#define VS_ST 72   // 8tig+g banks: conflict-free fragment reads

__global__ __launch_bounds__(128)
void flash_mma_kernel(const float* __restrict__ Q, const float* __restrict__ K,
                      const float* __restrict__ V, float* __restrict__ O) {
    __shared__ unsigned KsPs[FB_K][KS_ST];  // K tile; reused as P (warp rows w*16..)
    __shared__ unsigned Vs[FB_K][VS_ST];    // V tile [key][d]

    int qt   = blockIdx.x;
    int bh   = blockIdx.y;
    int b    = bh >> 4;
    int h    = bh & 15;
    int tid  = threadIdx.x;
    int lane = tid & 31;
    int w    = tid >> 5;
    int g    = lane >> 2;
    int tig  = lane & 3;

    size_t base = ((size_t)b * SEQ) * D_MODEL + h * D_HEAD;

    // ---- stage Q tile (64x64) into KsPs, extract A fragments, then release ----
    #pragma unroll
    for (int l = 0; l < 8; l++) {
        int f  = tid + l * 128;
        int r  = f >> 4;
        int c4 = (f & 15) * 4;
        float4 v = *(const float4*)(Q + base + (size_t)(qt * FB_Q + r) * D_MODEL + c4);
        unsigned* p = &KsPs[r][c4];
        p[0] = f2tf32(v.x); p[1] = f2tf32(v.y); p[2] = f2tf32(v.z); p[3] = f2tf32(v.w);
    }
    __syncthreads();
    unsigned aq[8][4];
    #pragma unroll
    for (int ks = 0; ks < 8; ks++) {
        int r0 = w * 16 + g;
        aq[ks][0] = KsPs[r0][ks * 8 + tig];
        aq[ks][1] = KsPs[r0 + 8][ks * 8 + tig];
        aq[ks][2] = KsPs[r0][ks * 8 + tig + 4];
        aq[ks][3] = KsPs[r0 + 8][ks * 8 + tig + 4];
    }
    __syncthreads();

    float o[8][4];
    #pragma unroll
    for (int nt = 0; nt < 8; nt++)
        #pragma unroll
        for (int r = 0; r < 4; r++) o[nt][r] = 0.f;

    float m0 = -1e30f, m1 = -1e30f, l0 = 0.f, l1 = 0.f;
    int qrow0 = qt * FB_Q + w * 16 + g;
    int qrow1 = qrow0 + 8;
    // scores in log2 domain: s * (1/8) * log2(e)
    const float SCL = 0.125f * 1.4426950408889634f;

    int ntile = qt + 1;
    for (int kt = 0; kt < ntile; kt++) {
        // ---- load K,V tile (64x64 each) ----
        #pragma unroll
        for (int l = 0; l < 8; l++) {
            int f  = tid + l * 128;
            int r  = f >> 4;
            int c4 = (f & 15) * 4;
            size_t ga = base + (size_t)(kt * FB_K + r) * D_MODEL + c4;
            float4 kv = *(const float4*)(K + ga);
            float4 vv = *(const float4*)(V + ga);
            unsigned* pk = &KsPs[r][c4];
            pk[0] = f2tf32(kv.x); pk[1] = f2tf32(kv.y); pk[2] = f2tf32(kv.z); pk[3] = f2tf32(kv.w);
            unsigned* pv = &Vs[r][c4];
            pv[0] = f2tf32(vv.x); pv[1] = f2tf32(vv.y); pv[2] = f2tf32(vv.z); pv[3] = f2tf32(vv.w);
        }
        __syncthreads();

        // ---- S = Q @ K^T  (16x64 per warp) ----
        float s[8][4];
        #pragma unroll
        for (int nt = 0; nt < 8; nt++)
            #pragma unroll
            for (int r = 0; r < 4; r++) s[nt][r] = 0.f;
        #pragma unroll
        for (int ks = 0; ks < 8; ks++) {
            #pragma unroll
            for (int nt = 0; nt < 8; nt++) {
                unsigned b0 = KsPs[nt * 8 + g][ks * 8 + tig];
                unsigned b1 = KsPs[nt * 8 + g][ks * 8 + tig + 4];
                mma_tf32(s[nt][0], s[nt][1], s[nt][2], s[nt][3],
                         aq[ks][0], aq[ks][1], aq[ks][2], aq[ks][3], b0, b1);
            }
        }
        __syncthreads();   // all warps done reading Ks before P overwrites it

        // ---- scale + causal mask ----
        bool diag = (kt == qt);
        #pragma unroll
        for (int nt = 0; nt < 8; nt++) {
            int kc = kt * FB_K + nt * 8 + tig * 2;
            s[nt][0] *= SCL; s[nt][1] *= SCL; s[nt][2] *= SCL; s[nt][3] *= SCL;
            if (diag) {
                if (kc     > qrow0) s[nt][0] = -1e30f;
                if (kc + 1 > qrow0) s[nt][1] = -1e30f;
                if (kc     > qrow1) s[nt][2] = -1e30f;
                if (kc + 1 > qrow1) s[nt][3] = -1e30f;
            }
        }

        // ---- online softmax (log2 domain) ----
        float rm0 = -1e30f, rm1 = -1e30f;
        #pragma unroll
        for (int nt = 0; nt < 8; nt++) {
            rm0 = fmaxf(rm0, fmaxf(s[nt][0], s[nt][1]));
            rm1 = fmaxf(rm1, fmaxf(s[nt][2], s[nt][3]));
        }
        rm0 = fmaxf(rm0, __shfl_xor_sync(0xffffffffu, rm0, 1));
        rm0 = fmaxf(rm0, __shfl_xor_sync(0xffffffffu, rm0, 2));
        rm1 = fmaxf(rm1, __shfl_xor_sync(0xffffffffu, rm1, 1));
        rm1 = fmaxf(rm1, __shfl_xor_sync(0xffffffffu, rm1, 2));
        float mn0 = fmaxf(m0, rm0), mn1 = fmaxf(m1, rm1);
        float sc0 = exp2f(m0 - mn0), sc1 = exp2f(m1 - mn1);
        m0 = mn0; m1 = mn1;

        float ls0 = 0.f, ls1 = 0.f;
        #pragma unroll
        for (int nt = 0; nt < 8; nt++) {
            s[nt][0] = exp2f(s[nt][0] - mn0);
            s[nt][1] = exp2f(s[nt][1] - mn0);
            s[nt][2] = exp2f(s[nt][2] - mn1);
            s[nt][3] = exp2f(s[nt][3] - mn1);
            ls0 += s[nt][0] + s[nt][1];
            ls1 += s[nt][2] + s[nt][3];
        }
        ls0 += __shfl_xor_sync(0xffffffffu, ls0, 1);
        ls0 += __shfl_xor_sync(0xffffffffu, ls0, 2);
        ls1 += __shfl_xor_sync(0xffffffffu, ls1, 1);
        ls1 += __shfl_xor_sync(0xffffffffu, ls1, 2);
        l0 = l0 * sc0 + ls0;
        l1 = l1 * sc1 + ls1;

        #pragma unroll
        for (int nt = 0; nt < 8; nt++) {
            o[nt][0] *= sc0; o[nt][1] *= sc0;
            o[nt][2] *= sc1; o[nt][3] *= sc1;
        }

        // ---- write P into warp-private rows of KsPs (tf32) ----
        {
            int r0 = w * 16 + g;
            #pragma unroll
            for (int nt = 0; nt < 8; nt++) {
                int cc = nt * 8 + tig * 2;
                KsPs[r0][cc]     = f2tf32(s[nt][0]);
                KsPs[r0][cc + 1] = f2tf32(s[nt][1]);
                KsPs[r0 + 8][cc]     = f2tf32(s[nt][2]);
                KsPs[r0 + 8][cc + 1] = f2tf32(s[nt][3]);
            }
        }
        __syncwarp();

        // ---- O += P @ V ----
        #pragma unroll
        for (int ks = 0; ks < 8; ks++) {
            int r0 = w * 16 + g;
            unsigned ap0 = KsPs[r0][ks * 8 + tig];
            unsigned ap1 = KsPs[r0 + 8][ks * 8 + tig];
            unsigned ap2 = KsPs[r0][ks * 8 + tig + 4];
            unsigned ap3 = KsPs[r0 + 8][ks * 8 + tig + 4];
            #pragma unroll
            for (int nt = 0; nt < 8; nt++) {
                unsigned b0 = Vs[ks * 8 + tig][nt * 8 + g];
                unsigned b1 = Vs[ks * 8 + tig + 4][nt * 8 + g];
                mma_tf32(o[nt][0], o[nt][1], o[nt][2], o[nt][3],
                         ap0, ap1, ap2, ap3, b0, b1);
            }
        }
        __syncthreads();   // everyone done with Ks(P)/Vs before next tile load
    }

    // ---- finalize ----
    float inv0 = 1.f / l0, inv1 = 1.f / l1;
    #pragma unroll
    for (int nt = 0; nt < 8; nt++) {
        int col = nt * 8 + tig * 2;
        float2 r0; r0.x = o[nt][0] * inv0; r0.y = o[nt][1] * inv0;
        float2 r1; r1.x = o[nt][2] * inv1; r1.y = o[nt][3] * inv1;
        *(float2*)(O + base + (size_t)qrow0 * D_MODEL + col) = r0;
        *(float2*)(O + base + (size_t)qrow1 * D_MODEL + col) = r1;
    }
}

// ---------------------------------------------------------------------------
// Launch
// ---------------------------------------------------------------------------
extern "C" void kernel_launch(void* const* d_in, const int* in_sizes, int n_in,
                              void* d_out, int out_size) {
    const float* x   = (const float*)d_in[0];
    const float* Wq  = (const float*)d_in[1];
    const float* bq  = (const float*)d_in[2];
    const float* Wk  = (const float*)d_in[3];
    const float* bk  = (const float*)d_in[4];
    const float* Wv  = (const float*)d_in[5];
    const float* bv  = (const float*)d_in[6];
    const float* Wo  = (const float*)d_in[7];
    const float* W1  = (const float*)d_in[8];
    const float* b1  = (const float*)d_in[9];
    const float* W2  = (const float*)d_in[10];
    const float* b2  = (const float*)d_in[11];
    const float* g1  = (const float*)d_in[12];
    const float* be1 = (const float*)d_in[13];
    const float* g2  = (const float*)d_in[14];
    const float* be2 = (const float*)d_in[15];
    float* out = (float*)d_out;

    float *ln, *q, *k, *v, *attn, *x1, *h;
    cudaGetSymbolAddress((void**)&ln,   g_ln);
    cudaGetSymbolAddress((void**)&q,    g_q);
    cudaGetSymbolAddress((void**)&k,    g_k);
    cudaGetSymbolAddress((void**)&v,    g_v);
    cudaGetSymbolAddress((void**)&attn, g_attn);
    cudaGetSymbolAddress((void**)&x1,   g_x1);
    cudaGetSymbolAddress((void**)&h,    g_h);

    dim3 gemm_d(D_MODEL / BN, T_TOKENS / BM);   // (8, 64)
    dim3 gemm_ff1(D_FF / BN, T_TOKENS / BM);    // (32, 64)

    // 1) ln1 = LN(x; g1, beta1)
    layernorm_kernel<<<T_TOKENS, 256>>>(x, g1, be1, ln);
    // 2) Q,K,V = ln1 @ W* + b*
    gemm_tf32_kernel<0><<<gemm_d, 256>>>(ln, Wq, bq, nullptr, q, T_TOKENS, D_MODEL, D_MODEL);
    gemm_tf32_kernel<0><<<gemm_d, 256>>>(ln, Wk, bk, nullptr, k, T_TOKENS, D_MODEL, D_MODEL);
    gemm_tf32_kernel<0><<<gemm_d, 256>>>(ln, Wv, bv, nullptr, v, T_TOKENS, D_MODEL, D_MODEL);
    // 3) causal flash attention (tensor cores)
    flash_mma_kernel<<<dim3(SEQ / FB_Q, BATCH * N_HEADS), 128>>>(q, k, v, attn);
    // 4) x1 = x + attn @ Wo      (no bias on o-proj)
    gemm_tf32_kernel<1><<<gemm_d, 256>>>(attn, Wo, nullptr, x, x1, T_TOKENS, D_MODEL, D_MODEL);
    // 5) ln2 = LN(x1; g2, beta2)
    layernorm_kernel<<<T_TOKENS, 256>>>(x1, g2, be2, ln);
    // 6) h = gelu(ln2 @ W1 + b1)
    gemm_tf32_kernel<2><<<gemm_ff1, 256>>>(ln, W1, b1, nullptr, h, T_TOKENS, D_FF, D_MODEL);
    // 7) out = x1 + h @ W2 + b2
    gemm_tf32_kernel<1><<<gemm_d, 256>>>(h, W2, b2, x1, out, T_TOKENS, D_MODEL, D_FF);
}

// round 4
// speedup vs baseline: 4.1456x; 1.4197x over previous
#include <cuda_runtime.h>
#include <cuda_bf16.h>
#include <math.h>

// ---------------------------------------------------------------------------
// Problem constants
// ---------------------------------------------------------------------------
#define T_TOKENS 8192   // B*S = 4*2048
#define D_MODEL  1024
#define D_FF     4096
#define N_HEADS  16
#define D_HEAD   64
#define SEQ      2048
#define BATCH    4

// ---------------------------------------------------------------------------
// Scratch (device globals; no allocation allowed)
// ---------------------------------------------------------------------------
__device__ float g_ln  [T_TOKENS * D_MODEL];
__device__ float g_q   [T_TOKENS * D_MODEL];
__device__ float g_k   [T_TOKENS * D_MODEL];
__device__ float g_v   [T_TOKENS * D_MODEL];
__device__ float g_attn[T_TOKENS * D_MODEL];
__device__ float g_x1  [T_TOKENS * D_MODEL];
__device__ float g_h   [T_TOKENS * D_FF];

// ---------------------------------------------------------------------------
// Common helpers
// ---------------------------------------------------------------------------
__device__ __forceinline__ unsigned f2tf32(float x) {
    unsigned r;
    asm("cvt.rna.tf32.f32 %0, %1;" : "=r"(r) : "f"(x));
    return r;
}

__device__ __forceinline__ unsigned smem_u32(const void* p) {
    return (unsigned)__cvta_generic_to_shared(p);
}

__device__ __forceinline__ void ldsm_x4(unsigned& r0, unsigned& r1,
                                        unsigned& r2, unsigned& r3, unsigned addr) {
    asm volatile("ldmatrix.sync.aligned.m8n8.x4.shared.b16 {%0,%1,%2,%3}, [%4];"
                 : "=r"(r0), "=r"(r1), "=r"(r2), "=r"(r3) : "r"(addr));
}

__device__ __forceinline__ void mma_tf32(float& c0, float& c1, float& c2, float& c3,
                                         unsigned a0, unsigned a1, unsigned a2, unsigned a3,
                                         unsigned b0, unsigned b1) {
    asm volatile(
        "mma.sync.aligned.m16n8k8.row.col.f32.tf32.tf32.f32 "
        "{%0,%1,%2,%3}, {%4,%5,%6,%7}, {%8,%9}, {%0,%1,%2,%3};"
        : "+f"(c0), "+f"(c1), "+f"(c2), "+f"(c3)
        : "r"(a0), "r"(a1), "r"(a2), "r"(a3), "r"(b0), "r"(b1));
}

__device__ __forceinline__ float gelu_tanh(float x) {
    float x3 = x * x * x;
    return 0.5f * x * (1.f + tanhf(0.7978845608028654f * (x + 0.044715f * x3)));
}

// ---------------------------------------------------------------------------
// Block reduction helper (256 threads)
// ---------------------------------------------------------------------------
__device__ __forceinline__ float blockReduceSum(float v) {
    __shared__ float sred[32];
    int lane = threadIdx.x & 31;
    int w    = threadIdx.x >> 5;
    #pragma unroll
    for (int o = 16; o > 0; o >>= 1) v += __shfl_xor_sync(0xffffffffu, v, o);
    if (lane == 0) sred[w] = v;
    __syncthreads();
    float r = (threadIdx.x < (blockDim.x >> 5)) ? sred[threadIdx.x] : 0.f;
    if (w == 0) {
        #pragma unroll
        for (int o = 4; o > 0; o >>= 1) r += __shfl_xor_sync(0xffffffffu, r, o);
        if (lane == 0) sred[0] = r;
    }
    __syncthreads();
    float out = sred[0];
    __syncthreads();
    return out;
}

// ---------------------------------------------------------------------------
// LayerNorm: one block per row (D=1024, 256 threads x float4)
// ---------------------------------------------------------------------------
__global__ __launch_bounds__(256)
void layernorm_kernel(const float* __restrict__ x, const float* __restrict__ g,
                      const float* __restrict__ b, float* __restrict__ out) {
    int row = blockIdx.x;
    int t   = threadIdx.x;
    const float* xr = x + (size_t)row * D_MODEL;
    float4 v = *(const float4*)(xr + t * 4);
    float sum = v.x + v.y + v.z + v.w;
    float mean = blockReduceSum(sum) * (1.f / (float)D_MODEL);
    float dx = v.x - mean, dy = v.y - mean, dz = v.z - mean, dw = v.w - mean;
    float sq = dx * dx + dy * dy + dz * dz + dw * dw;
    float var  = blockReduceSum(sq) * (1.f / (float)D_MODEL);
    float rstd = rsqrtf(var + 1e-6f);
    float4 gv = *(const float4*)(g + t * 4);
    float4 bv = *(const float4*)(b + t * 4);
    float4 o;
    o.x = dx * rstd * gv.x + bv.x;
    o.y = dy * rstd * gv.y + bv.y;
    o.z = dz * rstd * gv.z + bv.z;
    o.w = dw * rstd * gv.w + bv.w;
    *(float4*)(out + (size_t)row * D_MODEL + t * 4) = o;
}

// ---------------------------------------------------------------------------
// TF32 tensor-core GEMM, ldmatrix + XOR-swizzled smem + raw-fp32 (fastF32).
// C[M,N] = A[M,K] @ W[K,N]  (+bias) (+residual | +gelu)
// 128x128 block tile, GBK=16 double-buffered, 256 threads, warp 32x64.
// Smem layouts (both K-major, 16-word rows, chunk-swizzle c ^= (row>>1)&3):
//   As[m][k], Bs[n][k]. Fragments loaded with ldmatrix.x4 (b16 view of tf32).
// ---------------------------------------------------------------------------
#define BM 128
#define BN 128
#define GBK 16
#define STAGE_BYTES (BM * GBK * 4)

template <int EPI>
__device__ __forceinline__ void gemm_body(const float* __restrict__ A, const float* __restrict__ W,
                                          const float* __restrict__ bias, const float* __restrict__ res,
                                          float* __restrict__ C, int N, int K) {
    __shared__ unsigned As[2][BM * GBK];
    __shared__ unsigned Bs[2][BN * GBK];

    int tid  = threadIdx.x;
    int lane = tid & 31;
    int wid  = tid >> 5;
    int g    = lane >> 2;
    int tig  = lane & 3;

    int bm = blockIdx.y * BM;
    int bn = blockIdx.x * BN;
    int rowBase = (wid >> 1) * 32;
    int colBase = (wid & 1) * 64;

    float c[2][8][4];
    #pragma unroll
    for (int mt = 0; mt < 2; mt++)
        #pragma unroll
        for (int nt = 0; nt < 8; nt++)
            #pragma unroll
            for (int r = 0; r < 4; r++) c[mt][nt][r] = 0.f;

    // ---- loader indices ----
    // A: thread loads rows arow, arow+64 at chunk ac (float4 along k)
    int arow = tid >> 2;
    int ac   = tid & 3;
    int aw0  = arow * GBK + ((ac ^ ((arow >> 1) & 3)) << 2);
    int aw1  = aw0 + 64 * GBK;   // (arow+64) has identical swizzle bits
    // B: thread owns column n=bnr; loads k-quads bq0 and bq0+2 (LDG.32 coalesced)
    int bnr = tid & 127;
    int bq0 = tid >> 7;
    int bsw = (bnr >> 1) & 3;
    int bw0 = bnr * GBK + ((bq0 ^ bsw) << 2);
    int bw1 = bnr * GBK + (((bq0 + 2) ^ bsw) << 2);

    // ---- ldmatrix lane addresses (stage 0) ----
    unsigned aB = smem_u32(&As[0][0]);
    unsigned bB = smem_u32(&Bs[0][0]);
    unsigned addrA[2][2], addrB[4][2];
    #pragma unroll
    for (int mt = 0; mt < 2; mt++) {
        int r = rowBase + mt * 16 + (lane & 15);
        #pragma unroll
        for (int ks = 0; ks < 2; ks++) {
            int ch = ks * 2 + (lane >> 4);
            addrA[mt][ks] = aB + (unsigned)((r * GBK + ((ch ^ ((r >> 1) & 3)) << 2)) * 4);
        }
    }
    #pragma unroll
    for (int ntp = 0; ntp < 4; ntp++) {
        int r = colBase + ntp * 16 + ((lane >> 4) & 1) * 8 + (lane & 7);
        #pragma unroll
        for (int ks = 0; ks < 2; ks++) {
            int ch = ks * 2 + ((lane >> 3) & 1);
            addrB[ntp][ks] = bB + (unsigned)((r * GBK + ((ch ^ ((r >> 1) & 3)) << 2)) * 4);
        }
    }

    // ---- prologue: tile 0 ----
    float4 av0 = *(const float4*)(A + (size_t)(bm + arow) * K + ac * 4);
    float4 av1 = *(const float4*)(A + (size_t)(bm + arow + 64) * K + ac * 4);
    float bv[2][4];
    #pragma unroll
    for (int p = 0; p < 2; p++) {
        int q = bq0 + p * 2;
        #pragma unroll
        for (int j = 0; j < 4; j++)
            bv[p][j] = W[(size_t)(q * 4 + j) * N + bn + bnr];
    }
    *(uint4*)(&As[0][aw0]) = *(uint4*)&av0;
    *(uint4*)(&As[0][aw1]) = *(uint4*)&av1;
    {
        uint4 u0, u1;
        u0.x = __float_as_uint(bv[0][0]); u0.y = __float_as_uint(bv[0][1]);
        u0.z = __float_as_uint(bv[0][2]); u0.w = __float_as_uint(bv[0][3]);
        u1.x = __float_as_uint(bv[1][0]); u1.y = __float_as_uint(bv[1][1]);
        u1.z = __float_as_uint(bv[1][2]); u1.w = __float_as_uint(bv[1][3]);
        *(uint4*)(&Bs[0][bw0]) = u0;
        *(uint4*)(&Bs[0][bw1]) = u1;
    }
    __syncthreads();

    int nIter = K / GBK;
    for (int it = 0; it < nIter; it++) {
        int cur = it & 1;
        unsigned off = cur ? (unsigned)STAGE_BYTES : 0u;
        bool hasNext = (it + 1 < nIter);
        if (hasNext) {
            int k0 = (it + 1) * GBK;
            av0 = *(const float4*)(A + (size_t)(bm + arow) * K + k0 + ac * 4);
            av1 = *(const float4*)(A + (size_t)(bm + arow + 64) * K + k0 + ac * 4);
            #pragma unroll
            for (int p = 0; p < 2; p++) {
                int q = bq0 + p * 2;
                #pragma unroll
                for (int j = 0; j < 4; j++)
                    bv[p][j] = W[(size_t)(k0 + q * 4 + j) * N + bn + bnr];
            }
        }

        #pragma unroll
        for (int ks = 0; ks < 2; ks++) {
            unsigned a0[4], a1[4];
            ldsm_x4(a0[0], a0[1], a0[2], a0[3], addrA[0][ks] + off);
            ldsm_x4(a1[0], a1[1], a1[2], a1[3], addrA[1][ks] + off);
            #pragma unroll
            for (int ntp = 0; ntp < 4; ntp++) {
                unsigned b0, b1, b2, b3;
                ldsm_x4(b0, b1, b2, b3, addrB[ntp][ks] + off);
                int n0 = ntp * 2, n1 = ntp * 2 + 1;
                mma_tf32(c[0][n0][0], c[0][n0][1], c[0][n0][2], c[0][n0][3],
                         a0[0], a0[1], a0[2], a0[3], b0, b1);
                mma_tf32(c[0][n1][0], c[0][n1][1], c[0][n1][2], c[0][n1][3],
                         a0[0], a0[1], a0[2], a0[3], b2, b3);
                mma_tf32(c[1][n0][0], c[1][n0][1], c[1][n0][2], c[1][n0][3],
                         a1[0], a1[1], a1[2], a1[3], b0, b1);
                mma_tf32(c[1][n1][0], c[1][n1][1], c[1][n1][2], c[1][n1][3],
                         a1[0], a1[1], a1[2], a1[3], b2, b3);
            }
        }

        if (hasNext) {
            int nxt = 1 - cur;
            *(uint4*)(&As[nxt][aw0]) = *(uint4*)&av0;
            *(uint4*)(&As[nxt][aw1]) = *(uint4*)&av1;
            uint4 u0, u1;
            u0.x = __float_as_uint(bv[0][0]); u0.y = __float_as_uint(bv[0][1]);
            u0.z = __float_as_uint(bv[0][2]); u0.w = __float_as_uint(bv[0][3]);
            u1.x = __float_as_uint(bv[1][0]); u1.y = __float_as_uint(bv[1][1]);
            u1.z = __float_as_uint(bv[1][2]); u1.w = __float_as_uint(bv[1][3]);
            *(uint4*)(&Bs[nxt][bw0]) = u0;
            *(uint4*)(&Bs[nxt][bw1]) = u1;
        }
        __syncthreads();
    }

    // ---- epilogue ----
    #pragma unroll
    for (int mt = 0; mt < 2; mt++) {
        #pragma unroll
        for (int half = 0; half < 2; half++) {
            size_t row = (size_t)(bm + rowBase + mt * 16 + g + half * 8);
            #pragma unroll
            for (int nt = 0; nt < 8; nt++) {
                int col = bn + colBase + nt * 8 + tig * 2;
                float v0 = c[mt][nt][half * 2 + 0];
                float v1 = c[mt][nt][half * 2 + 1];
                if (bias) {
                    v0 += bias[col];
                    v1 += bias[col + 1];
                }
                if (EPI == 2) { v0 = gelu_tanh(v0); v1 = gelu_tanh(v1); }
                if (EPI == 1) {
                    const float2 rv = *(const float2*)(res + row * N + col);
                    v0 += rv.x; v1 += rv.y;
                }
                float2 o; o.x = v0; o.y = v1;
                *(float2*)(C + row * N + col) = o;
            }
        }
    }
}

template <int EPI>
__global__ __launch_bounds__(256, 2)
void gemm_tf32_kernel(const float* __restrict__ A, const float* __restrict__ W,
                      const float* __restrict__ bias, const float* __restrict__ res,
                      float* __restrict__ C, int N, int K) {
    gemm_body<EPI>(A, W, bias, res, C, N, K);
}

// Fused QKV: gridDim.z selects the projection (shared A tile traffic via L2).
__global__ __launch_bounds__(256, 2)
void gemm_qkv_kernel(const float* __restrict__ A,
                     const float* __restrict__ Wq, const float* __restrict__ bq, float* __restrict__ q,
                     const float* __restrict__ Wk, const float* __restrict__ bk, float* __restrict__ k,
                     const float* __restrict__ Wv, const float* __restrict__ bvp, float* __restrict__ v) {
    const float* W; const float* bi; float* C;
    if (blockIdx.z == 0)      { W = Wq; bi = bq; C = q; }
    else if (blockIdx.z == 1) { W = Wk; bi = bk; C = k; }
    else                      { W = Wv; bi = bvp; C = v; }
    gemm_body<0>(A, W, bi, nullptr, C, D_MODEL, D_MODEL);
}

// ---------------------------------------------------------------------------
// Flash attention v2 (causal), tf32 tensor cores (unchanged from round 3).
// ---------------------------------------------------------------------------
#define FB_Q 64
#define FB_K 64
#define KS_ST 68
#define VS_ST 72

__global__ __launch_bounds__(128)
void flash_mma_kernel(const float* __restrict__ Q, const float* __restrict__ K,
                      const float* __restrict__ V, float* __restrict__ O) {
    __shared__ unsigned KsPs[FB_K][KS_ST];
    __shared__ unsigned Vs[FB_K][VS_ST];

    int qt   = blockIdx.x;
    int bh   = blockIdx.y;
    int b    = bh >> 4;
    int h    = bh & 15;
    int tid  = threadIdx.x;
    int lane = tid & 31;
    int w    = tid >> 5;
    int g    = lane >> 2;
    int tig  = lane & 3;

    size_t base = ((size_t)b * SEQ) * D_MODEL + h * D_HEAD;

    #pragma unroll
    for (int l = 0; l < 8; l++) {
        int f  = tid + l * 128;
        int r  = f >> 4;
        int c4 = (f & 15) * 4;
        float4 v = *(const float4*)(Q + base + (size_t)(qt * FB_Q + r) * D_MODEL + c4);
        unsigned* p = &KsPs[r][c4];
        p[0] = f2tf32(v.x); p[1] = f2tf32(v.y); p[2] = f2tf32(v.z); p[3] = f2tf32(v.w);
    }
    __syncthreads();
    unsigned aq[8][4];
    #pragma unroll
    for (int ks = 0; ks < 8; ks++) {
        int r0 = w * 16 + g;
        aq[ks][0] = KsPs[r0][ks * 8 + tig];
        aq[ks][1] = KsPs[r0 + 8][ks * 8 + tig];
        aq[ks][2] = KsPs[r0][ks * 8 + tig + 4];
        aq[ks][3] = KsPs[r0 + 8][ks * 8 + tig + 4];
    }
    __syncthreads();

    float o[8][4];
    #pragma unroll
    for (int nt = 0; nt < 8; nt++)
        #pragma unroll
        for (int r = 0; r < 4; r++) o[nt][r] = 0.f;

    float m0 = -1e30f, m1 = -1e30f, l0 = 0.f, l1 = 0.f;
    int qrow0 = qt * FB_Q + w * 16 + g;
    int qrow1 = qrow0 + 8;
    const float SCL = 0.125f * 1.4426950408889634f;

    int ntile = qt + 1;
    for (int kt = 0; kt < ntile; kt++) {
        #pragma unroll
        for (int l = 0; l < 8; l++) {
            int f  = tid + l * 128;
            int r  = f >> 4;
            int c4 = (f & 15) * 4;
            size_t ga = base + (size_t)(kt * FB_K + r) * D_MODEL + c4;
            float4 kv = *(const float4*)(K + ga);
            float4 vv = *(const float4*)(V + ga);
            unsigned* pk = &KsPs[r][c4];
            pk[0] = f2tf32(kv.x); pk[1] = f2tf32(kv.y); pk[2] = f2tf32(kv.z); pk[3] = f2tf32(kv.w);
            unsigned* pv = &Vs[r][c4];
            pv[0] = f2tf32(vv.x); pv[1] = f2tf32(vv.y); pv[2] = f2tf32(vv.z); pv[3] = f2tf32(vv.w);
        }
        __syncthreads();

        float s[8][4];
        #pragma unroll
        for (int nt = 0; nt < 8; nt++)
            #pragma unroll
            for (int r = 0; r < 4; r++) s[nt][r] = 0.f;
        #pragma unroll
        for (int ks = 0; ks < 8; ks++) {
            #pragma unroll
            for (int nt = 0; nt < 8; nt++) {
                unsigned b0 = KsPs[nt * 8 + g][ks * 8 + tig];
                unsigned b1 = KsPs[nt * 8 + g][ks * 8 + tig + 4];
                mma_tf32(s[nt][0], s[nt][1], s[nt][2], s[nt][3],
                         aq[ks][0], aq[ks][1], aq[ks][2], aq[ks][3], b0, b1);
            }
        }
        __syncthreads();

        bool diag = (kt == qt);
        #pragma unroll
        for (int nt = 0; nt < 8; nt++) {
            int kc = kt * FB_K + nt * 8 + tig * 2;
            s[nt][0] *= SCL; s[nt][1] *= SCL; s[nt][2] *= SCL; s[nt][3] *= SCL;
            if (diag) {
                if (kc     > qrow0) s[nt][0] = -1e30f;
                if (kc + 1 > qrow0) s[nt][1] = -1e30f;
                if (kc     > qrow1) s[nt][2] = -1e30f;
                if (kc + 1 > qrow1) s[nt][3] = -1e30f;
            }
        }

        float rm0 = -1e30f, rm1 = -1e30f;
        #pragma unroll
        for (int nt = 0; nt < 8; nt++) {
            rm0 = fmaxf(rm0, fmaxf(s[nt][0], s[nt][1]));
            rm1 = fmaxf(rm1, fmaxf(s[nt][2], s[nt][3]));
        }
        rm0 = fmaxf(rm0, __shfl_xor_sync(0xffffffffu, rm0, 1));
        rm0 = fmaxf(rm0, __shfl_xor_sync(0xffffffffu, rm0, 2));
        rm1 = fmaxf(rm1, __shfl_xor_sync(0xffffffffu, rm1, 1));
        rm1 = fmaxf(rm1, __shfl_xor_sync(0xffffffffu, rm1, 2));
        float mn0 = fmaxf(m0, rm0), mn1 = fmaxf(m1, rm1);
        float sc0 = exp2f(m0 - mn0), sc1 = exp2f(m1 - mn1);
        m0 = mn0; m1 = mn1;

        float ls0 = 0.f, ls1 = 0.f;
        #pragma unroll
        for (int nt = 0; nt < 8; nt++) {
            s[nt][0] = exp2f(s[nt][0] - mn0);
            s[nt][1] = exp2f(s[nt][1] - mn0);
            s[nt][2] = exp2f(s[nt][2] - mn1);
            s[nt][3] = exp2f(s[nt][3] - mn1);
            ls0 += s[nt][0] + s[nt][1];
            ls1 += s[nt][2] + s[nt][3];
        }
        ls0 += __shfl_xor_sync(0xffffffffu, ls0, 1);
        ls0 += __shfl_xor_sync(0xffffffffu, ls0, 2);
        ls1 += __shfl_xor_sync(0xffffffffu, ls1, 1);
        ls1 += __shfl_xor_sync(0xffffffffu, ls1, 2);
        l0 = l0 * sc0 + ls0;
        l1 = l1 * sc1 + ls1;

        #pragma unroll
        for (int nt = 0; nt < 8; nt++) {
            o[nt][0] *= sc0; o[nt][1] *= sc0;
            o[nt][2] *= sc1; o[nt][3] *= sc1;
        }

        {
            int r0 = w * 16 + g;
            #pragma unroll
            for (int nt = 0; nt < 8; nt++) {
                int cc = nt * 8 + tig * 2;
                KsPs[r0][cc]     = f2tf32(s[nt][0]);
                KsPs[r0][cc + 1] = f2tf32(s[nt][1]);
                KsPs[r0 + 8][cc]     = f2tf32(s[nt][2]);
                KsPs[r0 + 8][cc + 1] = f2tf32(s[nt][3]);
            }
        }
        __syncwarp();

        #pragma unroll
        for (int ks = 0; ks < 8; ks++) {
            int r0 = w * 16 + g;
            unsigned ap0 = KsPs[r0][ks * 8 + tig];
            unsigned ap1 = KsPs[r0 + 8][ks * 8 + tig];
            unsigned ap2 = KsPs[r0][ks * 8 + tig + 4];
            unsigned ap3 = KsPs[r0 + 8][ks * 8 + tig + 4];
            #pragma unroll
            for (int nt = 0; nt < 8; nt++) {
                unsigned b0 = Vs[ks * 8 + tig][nt * 8 + g];
                unsigned b1 = Vs[ks * 8 + tig + 4][nt * 8 + g];
                mma_tf32(o[nt][0], o[nt][1], o[nt][2], o[nt][3],
                         ap0, ap1, ap2, ap3, b0, b1);
            }
        }
        __syncthreads();
    }

    float inv0 = 1.f / l0, inv1 = 1.f / l1;
    #pragma unroll
    for (int nt = 0; nt < 8; nt++) {
        int col = nt * 8 + tig * 2;
        float2 r0; r0.x = o[nt][0] * inv0; r0.y = o[nt][1] * inv0;
        float2 r1; r1.x = o[nt][2] * inv1; r1.y = o[nt][3] * inv1;
        *(float2*)(O + base + (size_t)qrow0 * D_MODEL + col) = r0;
        *(float2*)(O + base + (size_t)qrow1 * D_MODEL + col) = r1;
    }
}

// ---------------------------------------------------------------------------
// Launch
// ---------------------------------------------------------------------------
extern "C" void kernel_launch(void* const* d_in, const int* in_sizes, int n_in,
                              void* d_out, int out_size) {
    const float* x   = (const float*)d_in[0];
    const float* Wq  = (const float*)d_in[1];
    const float* bq  = (const float*)d_in[2];
    const float* Wk  = (const float*)d_in[3];
    const float* bk  = (const float*)d_in[4];
    const float* Wv  = (const float*)d_in[5];
    const float* bv  = (const float*)d_in[6];
    const float* Wo  = (const float*)d_in[7];
    const float* W1  = (const float*)d_in[8];
    const float* b1  = (const float*)d_in[9];
    const float* W2  = (const float*)d_in[10];
    const float* b2  = (const float*)d_in[11];
    const float* g1  = (const float*)d_in[12];
    const float* be1 = (const float*)d_in[13];
    const float* g2  = (const float*)d_in[14];
    const float* be2 = (const float*)d_in[15];
    float* out = (float*)d_out;

    float *ln, *q, *k, *v, *attn, *x1, *h;
    cudaGetSymbolAddress((void**)&ln,   g_ln);
    cudaGetSymbolAddress((void**)&q,    g_q);
    cudaGetSymbolAddress((void**)&k,    g_k);
    cudaGetSymbolAddress((void**)&v,    g_v);
    cudaGetSymbolAddress((void**)&attn, g_attn);
    cudaGetSymbolAddress((void**)&x1,   g_x1);
    cudaGetSymbolAddress((void**)&h,    g_h);

    dim3 gemm_d(D_MODEL / BN, T_TOKENS / BM);        // (8, 64)
    dim3 gemm_qkv(D_MODEL / BN, T_TOKENS / BM, 3);   // (8, 64, 3)
    dim3 gemm_ff1(D_FF / BN, T_TOKENS / BM);         // (32, 64)

    // 1) ln1 = LN(x; g1, beta1)
    layernorm_kernel<<<T_TOKENS, 256>>>(x, g1, be1, ln);
    // 2) Q,K,V = ln1 @ W* + b*   (fused launch)
    gemm_qkv_kernel<<<gemm_qkv, 256>>>(ln, Wq, bq, q, Wk, bk, k, Wv, bv, v);
    // 3) causal flash attention (tensor cores)
    flash_mma_kernel<<<dim3(SEQ / FB_Q, BATCH * N_HEADS), 128>>>(q, k, v, attn);
    // 4) x1 = x + attn @ Wo      (no bias on o-proj)
    gemm_tf32_kernel<1><<<gemm_d, 256>>>(attn, Wo, nullptr, x, x1, D_MODEL, D_MODEL);
    // 5) ln2 = LN(x1; g2, beta2)
    layernorm_kernel<<<T_TOKENS, 256>>>(x1, g2, be2, ln);
    // 6) h = gelu(ln2 @ W1 + b1)
    gemm_tf32_kernel<2><<<gemm_ff1, 256>>>(ln, W1, b1, nullptr, h, D_FF, D_MODEL);
    // 7) out = x1 + h @ W2 + b2
    gemm_tf32_kernel<1><<<gemm_d, 256>>>(h, W2, b2, x1, out, D_MODEL, D_FF);
}